// round 8
// baseline (speedup 1.0000x reference)
#include <cuda_runtime.h>
#include <cuda_fp16.h>
#include <cstdint>

constexpr int S  = 24;
constexpr int Bn = 256;
constexpr int Dm = 1024;
constexpr int Ln = 12;
constexpr int Vn = 32000;
constexpr int DH = 64;
constexpr int Mr = S * Bn;          // 6144
constexpr int QKVN = 3 * Dm;        // 3072
constexpr int WROWS = Ln * QKVN;    // 36864

constexpr int BM = 128, BN = 128, BK = 64, STAGES = 3;
constexpr int STAGE_BYTES = (BM * BK + BN * BK) * 2;      // 32 KB
constexpr int SMEM_BYTES  = STAGES * STAGE_BYTES;         // 96 KB

// ---------------- scratch (device globals; no allocation) ----------------
__device__ float g_x[(size_t)Mr * Dm];
__device__ float g_qkv[(size_t)Mr * QKVN];
__device__ uint16_t g_xh16[(size_t)Mr * Dm];   // fp16 hi of x
__device__ uint16_t g_xl16[(size_t)Mr * Dm];   // fp16 lo of x
__device__ uint16_t g_w16[(size_t)WROWS * Dm]; // fp16 qkv weights
__device__ uint16_t g_ow16[(size_t)Vn * Dm];   // fp16 out_w

__device__ __forceinline__ uint32_t smem_u32(const void* p) {
    uint32_t a;
    asm("{ .reg .u64 t; cvta.to.shared.u64 t, %1; cvt.u32.u64 %0, t; }" : "=r"(a) : "l"(p));
    return a;
}

// xor swizzle for 128-byte rows (BK=64 b16): 16B chunk index xored with row%8
__device__ __forceinline__ uint32_t swz(int row, int g) {
    return (uint32_t)(row * 128 + ((g ^ (row & 7)) << 4));
}

// ---------------------------------------------------------------------------
// Multi-segment fp16 GEMM via mma.sync: C[128,128] = sum_seg Aseg . Wseg^T + b
// NIT_ iterations of BK=64 (16 per segment: NIT_=16 -> 1 seg, 32 -> 2 segs).
// 256 threads, 8 warps (4m x 2n), warp tile 32x64, cp.async 3-stage.
// ---------------------------------------------------------------------------
template<int NIT_>
__device__ __forceinline__ void gemm_core(
    const uint16_t* __restrict__ A0, const uint16_t* __restrict__ A1,
    const uint16_t* __restrict__ W0, const uint16_t* __restrict__ W1,
    const float* __restrict__ bias, float* __restrict__ C, int ldC)
{
    extern __shared__ char smem[];
    const uint32_t sb = smem_u32(smem);
    const int tid = threadIdx.x;
    const int lane = tid & 31;
    const int wid = tid >> 5;
    const int wm = wid & 3;         // warp m index -> rows 32*wm
    const int wn = wid >> 2;        // warp n index -> cols 64*wn

    auto loadStage = [&](int it, int slot) {
        const int seg = it >> 4;                 // 16 BK-chunks per segment
        const int k0  = (it & 15) * BK;
        const uint16_t* A = (seg == 0) ? A0 : A1;
        const uint16_t* W = (seg == 0) ? W0 : W1;
        const uint32_t sa = sb + slot * STAGE_BYTES;
        const uint32_t sw = sa + BM * BK * 2;
#pragma unroll
        for (int i = 0; i < 4; i++) {
            int ch = tid + i * 256;
            int r = ch >> 3, cb = ch & 7;
            const void* gp = A + (size_t)r * Dm + k0 + cb * 8;
            asm volatile("cp.async.cg.shared.global [%0], [%1], 16;"
                         :: "r"(sa + swz(r, cb)), "l"(gp));
        }
#pragma unroll
        for (int i = 0; i < 4; i++) {
            int ch = tid + i * 256;
            int r = ch >> 3, cb = ch & 7;
            const void* gp = W + (size_t)r * Dm + k0 + cb * 8;
            asm volatile("cp.async.cg.shared.global [%0], [%1], 16;"
                         :: "r"(sw + swz(r, cb)), "l"(gp));
        }
        asm volatile("cp.async.commit_group;");
    };

    float acc[2][8][4];
#pragma unroll
    for (int a = 0; a < 2; a++)
#pragma unroll
        for (int b = 0; b < 8; b++)
#pragma unroll
            for (int c = 0; c < 4; c++) acc[a][b][c] = 0.f;

    loadStage(0, 0);
    loadStage(1, 1);

    for (int it = 0; it < NIT_; it++) {
        if (it + 2 < NIT_) asm volatile("cp.async.wait_group 1;");
        else               asm volatile("cp.async.wait_group 0;");
        __syncthreads();
        if (it + 2 < NIT_) loadStage(it + 2, (it + 2) % STAGES);

        const uint32_t sa = sb + (it % STAGES) * STAGE_BYTES;
        const uint32_t sw = sa + BM * BK * 2;
#pragma unroll
        for (int q = 0; q < 4; q++) {           // k16 steps within BK=64
            uint32_t afr[2][4], bfr[8][2];
#pragma unroll
            for (int mi = 0; mi < 2; mi++) {
                int m = wm * 32 + mi * 16 + (lane & 15);
                int g = 2 * q + (lane >> 4);
                asm volatile("ldmatrix.sync.aligned.m8n8.x4.shared.b16 {%0,%1,%2,%3}, [%4];"
                             : "=r"(afr[mi][0]), "=r"(afr[mi][1]),
                               "=r"(afr[mi][2]), "=r"(afr[mi][3])
                             : "r"(sa + swz(m, g)));
            }
#pragma unroll
            for (int nj = 0; nj < 8; nj += 2) {
                int n = wn * 64 + nj * 8 + (lane & 7) + ((lane & 16) >> 1);
                int g = 2 * q + ((lane >> 3) & 1);
                asm volatile("ldmatrix.sync.aligned.m8n8.x4.shared.b16 {%0,%1,%2,%3}, [%4];"
                             : "=r"(bfr[nj][0]), "=r"(bfr[nj][1]),
                               "=r"(bfr[nj + 1][0]), "=r"(bfr[nj + 1][1])
                             : "r"(sw + swz(n, g)));
            }
#pragma unroll
            for (int mi = 0; mi < 2; mi++)
#pragma unroll
                for (int nj = 0; nj < 8; nj++) {
                    asm volatile(
                        "mma.sync.aligned.m16n8k16.row.col.f32.f16.f16.f32 "
                        "{%0,%1,%2,%3}, {%4,%5,%6,%7}, {%8,%9}, {%0,%1,%2,%3};"
                        : "+f"(acc[mi][nj][0]), "+f"(acc[mi][nj][1]),
                          "+f"(acc[mi][nj][2]), "+f"(acc[mi][nj][3])
                        : "r"(afr[mi][0]), "r"(afr[mi][1]),
                          "r"(afr[mi][2]), "r"(afr[mi][3]),
                          "r"(bfr[nj][0]), "r"(bfr[nj][1]));
                }
        }
    }

    // epilogue: c0,c1 = (row, col..col+1), c2,c3 = (row+8, ...)
    const int r0 = wm * 32 + (lane >> 2);
    const int cl = 2 * (lane & 3);
#pragma unroll
    for (int mi = 0; mi < 2; mi++)
#pragma unroll
        for (int ro = 0; ro < 2; ro++) {
            int row = r0 + mi * 16 + ro * 8;
            float* crow = C + (size_t)row * ldC;
#pragma unroll
            for (int nj = 0; nj < 8; nj++) {
                int col = wn * 64 + nj * 8 + cl;
                float2 o;
                o.x = acc[mi][nj][ro * 2 + 0] + bias[col];
                o.y = acc[mi][nj][ro * 2 + 1] + bias[col + 1];
                *reinterpret_cast<float2*>(crow + col) = o;
            }
        }
}

// QKV projection (fp16 2-pass: (Xh + Xl) . W16): grid (48, 24)
__global__ void __launch_bounds__(256, 2) gemm_qkv_tc(
    int layer, const float* __restrict__ qb, const float* __restrict__ kb,
    const float* __restrict__ vb)
{
    const int mT = blockIdx.x, nT = blockIdx.y;
    const size_t aOff = (size_t)mT * 128 * Dm;
    const size_t wOff = (size_t)(layer * QKVN + nT * 128) * Dm;
    const int mat = nT >> 3;
    const float* bias = ((mat == 0) ? qb : (mat == 1) ? kb : vb)
                        + (size_t)layer * Dm + (nT & 7) * 128;
    float* C = g_qkv + (size_t)mT * 128 * QKVN + nT * 128;
    gemm_core<32>(g_xh16 + aOff, g_xl16 + aOff,
                  g_w16 + wOff, g_w16 + wOff, bias, C, QKVN);
}

// Final logits (fp16 single pass: Xh . W16): grid (48, 250)
__global__ void __launch_bounds__(256, 2) gemm_out_tc(
    const float* __restrict__ ob, float* __restrict__ out)
{
    const int mT = blockIdx.x, nT = blockIdx.y;
    const size_t aOff = (size_t)mT * 128 * Dm;
    const size_t wOff = (size_t)nT * 128 * Dm;
    float* C = out + (size_t)mT * 128 * Vn + nT * 128;
    gemm_core<16>(g_xh16 + aOff, g_xh16 + aOff,
                  g_ow16 + wOff, g_ow16 + wOff, ob + nT * 128, C, Vn);
}

// ---------------------------------------------------------------------------
// Weight prep: fp32 -> fp16 single plane
// ---------------------------------------------------------------------------
__global__ void conv_wqkv16(const float* __restrict__ qw, const float* __restrict__ kw,
                            const float* __restrict__ vw) {
    size_t t = (size_t)blockIdx.x * 256 + threadIdx.x;
    size_t e = t * 4;
    int row = (int)(e >> 10);
    int col = (int)(e & 1023);
    int l   = row / 3072;
    int rem = row - l * 3072;
    int mat = rem >> 10;
    int n   = rem & 1023;
    const float* src = ((mat == 0) ? qw : (mat == 1) ? kw : vw)
                       + (((size_t)l * 1024 + n) << 10) + col;
    float4 v = *reinterpret_cast<const float4*>(src);
    size_t d = ((size_t)row << 10) + col;
    *reinterpret_cast<__half2*>(g_w16 + d)     = __floats2half2_rn(v.x, v.y);
    *reinterpret_cast<__half2*>(g_w16 + d + 2) = __floats2half2_rn(v.z, v.w);
}

__global__ void conv_wout16(const float* __restrict__ ow) {
    size_t e = ((size_t)blockIdx.x * 256 + threadIdx.x) * 4;   // < Vn*Dm
    float4 v = *reinterpret_cast<const float4*>(ow + e);
    *reinterpret_cast<__half2*>(g_ow16 + e)     = __floats2half2_rn(v.x, v.y);
    *reinterpret_cast<__half2*>(g_ow16 + e + 2) = __floats2half2_rn(v.z, v.w);
}

// ---------------------------------------------------------------------------
// Embedding + fp16 hi/lo split
// ---------------------------------------------------------------------------
__global__ void embed_kernel(const int* __restrict__ inputs,
                             const float* __restrict__ tok,
                             const float* __restrict__ pe) {
    int row = blockIdx.x;          // s*B + b
    int s = row / Bn;
    int t = inputs[row];
    const float4* te = reinterpret_cast<const float4*>(tok + (size_t)t * Dm);
    const float4* pp = reinterpret_cast<const float4*>(pe + (size_t)s * Dm);
    float4 a = te[threadIdx.x];
    float4 b = pp[threadIdx.x];
    float4 o = make_float4(a.x + b.x, a.y + b.y, a.z + b.z, a.w + b.w);
    size_t d = (size_t)row * Dm + threadIdx.x * 4;
    *reinterpret_cast<float4*>(g_x + d) = o;
    float f[4] = {o.x, o.y, o.z, o.w};
    __half h[4], l[4];
#pragma unroll
    for (int i = 0; i < 4; i++) {
        h[i] = __float2half_rn(f[i]);
        l[i] = __float2half_rn(f[i] - __half2float(h[i]));
    }
    *reinterpret_cast<__half2*>(g_xh16 + d)     = __half2(h[0], h[1]);
    *reinterpret_cast<__half2*>(g_xh16 + d + 2) = __half2(h[2], h[3]);
    *reinterpret_cast<__half2*>(g_xl16 + d)     = __half2(l[0], l[1]);
    *reinterpret_cast<__half2*>(g_xl16 + d + 2) = __half2(l[2], l[3]);
}

// ---------------------------------------------------------------------------
// Attention per (b,h): scores->softmax->AV->residual + fp16 split of new x
// ---------------------------------------------------------------------------
__global__ void __launch_bounds__(256) attn_kernel() {
    int bh = blockIdx.x;
    int b = bh >> 4;
    int h = bh & 15;
    __shared__ float qs[S][DH + 1];
    __shared__ float ks[S][DH + 1];
    __shared__ float vs[S][DH + 1];
    __shared__ float sc[S][S];
    int tid = threadIdx.x;

    for (int p = tid; p < S * DH; p += 256) {
        int s = p >> 6, d = p & 63;
        size_t g = (size_t)(s * Bn + b) * QKVN + h * DH + d;
        qs[s][d] = g_qkv[g];
        ks[s][d] = g_qkv[g + 1024];
        vs[s][d] = g_qkv[g + 2048];
    }
    __syncthreads();

    constexpr float scale = 0.03125f;   // 1/sqrt(1024)
    for (int p = tid; p < S * S; p += 256) {
        int si = p / S, ti = p - si * S;
        float acc = 0.f;
#pragma unroll
        for (int d = 0; d < DH; d++) acc = fmaf(qs[si][d], ks[ti][d], acc);
        sc[si][ti] = acc * scale;
    }
    __syncthreads();

    if (tid < S) {
        float mx = -1e30f;
        for (int t = 0; t < S; t++) mx = fmaxf(mx, sc[tid][t]);
        float sum = 0.f;
        for (int t = 0; t < S; t++) {
            float e = expf(sc[tid][t] - mx);
            sc[tid][t] = e;
            sum += e;
        }
        float inv = 1.f / sum;
        for (int t = 0; t < S; t++) sc[tid][t] *= inv;
    }
    __syncthreads();

    for (int p = tid; p < S * DH; p += 256) {
        int s = p >> 6, d = p & 63;
        float acc = 0.f;
#pragma unroll
        for (int t = 0; t < S; t++) acc = fmaf(sc[s][t], vs[t][d], acc);
        size_t xi = (size_t)(s * Bn + b) * Dm + h * DH + d;
        float nv = g_x[xi] + acc;
        g_x[xi] = nv;
        __half hh = __float2half_rn(nv);
        __half ll = __float2half_rn(nv - __half2float(hh));
        g_xh16[xi] = __half_as_ushort(hh);
        g_xl16[xi] = __half_as_ushort(ll);
    }
}

// ---------------------------------------------------------------------------
extern "C" void kernel_launch(void* const* d_in, const int* in_sizes, int n_in,
                              void* d_out, int out_size) {
    const int*   inputs = (const int*)d_in[0];
    // d_in[1] = mask (reference drops it)
    const float* tok = (const float*)d_in[2];
    const float* pe  = (const float*)d_in[3];
    const float* qw  = (const float*)d_in[4];
    const float* qb  = (const float*)d_in[5];
    const float* kw  = (const float*)d_in[6];
    const float* kb  = (const float*)d_in[7];
    const float* vw  = (const float*)d_in[8];
    const float* vb  = (const float*)d_in[9];
    const float* ow  = (const float*)d_in[10];
    const float* ob  = (const float*)d_in[11];
    float* out = (float*)d_out;

    cudaFuncSetAttribute(gemm_qkv_tc, cudaFuncAttributeMaxDynamicSharedMemorySize, SMEM_BYTES);
    cudaFuncSetAttribute(gemm_out_tc, cudaFuncAttributeMaxDynamicSharedMemorySize, SMEM_BYTES);

    conv_wqkv16<<<WROWS, 256>>>(qw, kw, vw);
    conv_wout16<<<Vn, 256>>>(ow);
    embed_kernel<<<Mr, 256>>>(inputs, tok, pe);

    for (int l = 0; l < Ln; l++) {
        gemm_qkv_tc<<<dim3(48, 24), 256, SMEM_BYTES>>>(l, qb, kb, vb);
        attn_kernel<<<Bn * 16, 256>>>();
    }
    gemm_out_tc<<<dim3(48, 250), 256, SMEM_BYTES>>>(ob, out);
}

// round 9
// speedup vs baseline: 1.3066x; 1.3066x over previous
#include <cuda_runtime.h>
#include <cuda_fp16.h>
#include <cstdint>

constexpr int S  = 24;
constexpr int Bn = 256;
constexpr int Dm = 1024;
constexpr int Ln = 12;
constexpr int Vn = 32000;
constexpr int DH = 64;
constexpr int Mr = S * Bn;          // 6144
constexpr int QKVN = 3 * Dm;        // 3072
constexpr int WROWS = Ln * QKVN;    // 36864

constexpr int BM = 128, BN = 128, BK = 64, STAGES = 3;
constexpr int STAGE_BYTES = (BM * BK + BN * BK) * 2;      // 32 KB
constexpr int SMEM_BYTES  = STAGES * STAGE_BYTES;         // 96 KB

// ---------------- scratch (device globals; no allocation) ----------------
__device__ float g_x[(size_t)Mr * Dm];
__device__ float g_qkv[(size_t)Mr * QKVN];
__device__ uint16_t g_xh16[(size_t)Mr * Dm];   // fp16 x
__device__ uint16_t g_w16[(size_t)WROWS * Dm]; // fp16 qkv weights
__device__ uint16_t g_ow16[(size_t)Vn * Dm];   // fp16 out_w

__device__ __forceinline__ uint32_t smem_u32(const void* p) {
    uint32_t a;
    asm("{ .reg .u64 t; cvta.to.shared.u64 t, %1; cvt.u32.u64 %0, t; }" : "=r"(a) : "l"(p));
    return a;
}

// xor swizzle for 128-byte rows (BK=64 b16): 16B chunk index xored with row%8
__device__ __forceinline__ uint32_t swz(int row, int g) {
    return (uint32_t)(row * 128 + ((g ^ (row & 7)) << 4));
}

// ---------------------------------------------------------------------------
// fp16 GEMM via mma.sync: C[128,128] = A[128,1024] . W[128,1024]^T + bias
// 16 iterations of BK=64.  256 threads, 8 warps (4m x 2n), warp tile 32x64,
// cp.async 3-stage pipeline.
// ---------------------------------------------------------------------------
__device__ __forceinline__ void gemm_core(
    const uint16_t* __restrict__ A, const uint16_t* __restrict__ W,
    const float* __restrict__ bias, float* __restrict__ C, int ldC)
{
    constexpr int NIT_ = 16;
    extern __shared__ char smem[];
    const uint32_t sb = smem_u32(smem);
    const int tid = threadIdx.x;
    const int lane = tid & 31;
    const int wid = tid >> 5;
    const int wm = wid & 3;         // warp m index -> rows 32*wm
    const int wn = wid >> 2;        // warp n index -> cols 64*wn

    auto loadStage = [&](int it, int slot) {
        const int k0 = it * BK;
        const uint32_t sa = sb + slot * STAGE_BYTES;
        const uint32_t sw = sa + BM * BK * 2;
#pragma unroll
        for (int i = 0; i < 4; i++) {
            int ch = tid + i * 256;
            int r = ch >> 3, cb = ch & 7;
            const void* gp = A + (size_t)r * Dm + k0 + cb * 8;
            asm volatile("cp.async.cg.shared.global [%0], [%1], 16;"
                         :: "r"(sa + swz(r, cb)), "l"(gp));
        }
#pragma unroll
        for (int i = 0; i < 4; i++) {
            int ch = tid + i * 256;
            int r = ch >> 3, cb = ch & 7;
            const void* gp = W + (size_t)r * Dm + k0 + cb * 8;
            asm volatile("cp.async.cg.shared.global [%0], [%1], 16;"
                         :: "r"(sw + swz(r, cb)), "l"(gp));
        }
        asm volatile("cp.async.commit_group;");
    };

    float acc[2][8][4];
#pragma unroll
    for (int a = 0; a < 2; a++)
#pragma unroll
        for (int b = 0; b < 8; b++)
#pragma unroll
            for (int c = 0; c < 4; c++) acc[a][b][c] = 0.f;

    loadStage(0, 0);
    loadStage(1, 1);

    for (int it = 0; it < NIT_; it++) {
        if (it + 2 < NIT_) asm volatile("cp.async.wait_group 1;");
        else               asm volatile("cp.async.wait_group 0;");
        __syncthreads();
        if (it + 2 < NIT_) loadStage(it + 2, (it + 2) % STAGES);

        const uint32_t sa = sb + (it % STAGES) * STAGE_BYTES;
        const uint32_t sw = sa + BM * BK * 2;
#pragma unroll
        for (int q = 0; q < 4; q++) {           // k16 steps within BK=64
            uint32_t afr[2][4], bfr[8][2];
#pragma unroll
            for (int mi = 0; mi < 2; mi++) {
                int m = wm * 32 + mi * 16 + (lane & 15);
                int g = 2 * q + (lane >> 4);
                asm volatile("ldmatrix.sync.aligned.m8n8.x4.shared.b16 {%0,%1,%2,%3}, [%4];"
                             : "=r"(afr[mi][0]), "=r"(afr[mi][1]),
                               "=r"(afr[mi][2]), "=r"(afr[mi][3])
                             : "r"(sa + swz(m, g)));
            }
#pragma unroll
            for (int nj = 0; nj < 8; nj += 2) {
                int n = wn * 64 + nj * 8 + (lane & 7) + ((lane & 16) >> 1);
                int g = 2 * q + ((lane >> 3) & 1);
                asm volatile("ldmatrix.sync.aligned.m8n8.x4.shared.b16 {%0,%1,%2,%3}, [%4];"
                             : "=r"(bfr[nj][0]), "=r"(bfr[nj][1]),
                               "=r"(bfr[nj + 1][0]), "=r"(bfr[nj + 1][1])
                             : "r"(sw + swz(n, g)));
            }
#pragma unroll
            for (int mi = 0; mi < 2; mi++)
#pragma unroll
                for (int nj = 0; nj < 8; nj++) {
                    asm volatile(
                        "mma.sync.aligned.m16n8k16.row.col.f32.f16.f16.f32 "
                        "{%0,%1,%2,%3}, {%4,%5,%6,%7}, {%8,%9}, {%0,%1,%2,%3};"
                        : "+f"(acc[mi][nj][0]), "+f"(acc[mi][nj][1]),
                          "+f"(acc[mi][nj][2]), "+f"(acc[mi][nj][3])
                        : "r"(afr[mi][0]), "r"(afr[mi][1]),
                          "r"(afr[mi][2]), "r"(afr[mi][3]),
                          "r"(bfr[nj][0]), "r"(bfr[nj][1]));
                }
        }
    }

    // epilogue
    const int r0 = wm * 32 + (lane >> 2);
    const int cl = 2 * (lane & 3);
#pragma unroll
    for (int mi = 0; mi < 2; mi++)
#pragma unroll
        for (int ro = 0; ro < 2; ro++) {
            int row = r0 + mi * 16 + ro * 8;
            float* crow = C + (size_t)row * ldC;
#pragma unroll
            for (int nj = 0; nj < 8; nj++) {
                int col = wn * 64 + nj * 8 + cl;
                float2 o;
                o.x = acc[mi][nj][ro * 2 + 0] + bias[col];
                o.y = acc[mi][nj][ro * 2 + 1] + bias[col + 1];
                *reinterpret_cast<float2*>(crow + col) = o;
            }
        }
}

// QKV projection (fp16 1-pass): grid (48, 24)
__global__ void __launch_bounds__(256, 2) gemm_qkv_tc(
    int layer, const float* __restrict__ qb, const float* __restrict__ kb,
    const float* __restrict__ vb)
{
    const int mT = blockIdx.x, nT = blockIdx.y;
    const size_t aOff = (size_t)mT * 128 * Dm;
    const size_t wOff = (size_t)(layer * QKVN + nT * 128) * Dm;
    const int mat = nT >> 3;
    const float* bias = ((mat == 0) ? qb : (mat == 1) ? kb : vb)
                        + (size_t)layer * Dm + (nT & 7) * 128;
    float* C = g_qkv + (size_t)mT * 128 * QKVN + nT * 128;
    gemm_core(g_xh16 + aOff, g_w16 + wOff, bias, C, QKVN);
}

// Final logits (fp16 1-pass): grid (48, 250)
__global__ void __launch_bounds__(256, 2) gemm_out_tc(
    const float* __restrict__ ob, float* __restrict__ out)
{
    const int mT = blockIdx.x, nT = blockIdx.y;
    const size_t aOff = (size_t)mT * 128 * Dm;
    const size_t wOff = (size_t)nT * 128 * Dm;
    float* C = out + (size_t)mT * 128 * Vn + nT * 128;
    gemm_core(g_xh16 + aOff, g_ow16 + wOff, ob + nT * 128, C, Vn);
}

// ---------------------------------------------------------------------------
// Weight prep: fp32 -> fp16
// ---------------------------------------------------------------------------
__global__ void conv_wqkv16(const float* __restrict__ qw, const float* __restrict__ kw,
                            const float* __restrict__ vw) {
    size_t t = (size_t)blockIdx.x * 256 + threadIdx.x;
    size_t e = t * 4;
    int row = (int)(e >> 10);
    int col = (int)(e & 1023);
    int l   = row / 3072;
    int rem = row - l * 3072;
    int mat = rem >> 10;
    int n   = rem & 1023;
    const float* src = ((mat == 0) ? qw : (mat == 1) ? kw : vw)
                       + (((size_t)l * 1024 + n) << 10) + col;
    float4 v = *reinterpret_cast<const float4*>(src);
    size_t d = ((size_t)row << 10) + col;
    *reinterpret_cast<__half2*>(g_w16 + d)     = __floats2half2_rn(v.x, v.y);
    *reinterpret_cast<__half2*>(g_w16 + d + 2) = __floats2half2_rn(v.z, v.w);
}

__global__ void conv_wout16(const float* __restrict__ ow) {
    size_t e = ((size_t)blockIdx.x * 256 + threadIdx.x) * 4;   // < Vn*Dm
    float4 v = *reinterpret_cast<const float4*>(ow + e);
    *reinterpret_cast<__half2*>(g_ow16 + e)     = __floats2half2_rn(v.x, v.y);
    *reinterpret_cast<__half2*>(g_ow16 + e + 2) = __floats2half2_rn(v.z, v.w);
}

// ---------------------------------------------------------------------------
// Embedding + fp16 convert
// ---------------------------------------------------------------------------
__global__ void embed_kernel(const int* __restrict__ inputs,
                             const float* __restrict__ tok,
                             const float* __restrict__ pe) {
    int row = blockIdx.x;          // s*B + b
    int s = row / Bn;
    int t = inputs[row];
    const float4* te = reinterpret_cast<const float4*>(tok + (size_t)t * Dm);
    const float4* pp = reinterpret_cast<const float4*>(pe + (size_t)s * Dm);
    float4 a = te[threadIdx.x];
    float4 b = pp[threadIdx.x];
    float4 o = make_float4(a.x + b.x, a.y + b.y, a.z + b.z, a.w + b.w);
    size_t d = (size_t)row * Dm + threadIdx.x * 4;
    *reinterpret_cast<float4*>(g_x + d) = o;
    *reinterpret_cast<__half2*>(g_xh16 + d)     = __floats2half2_rn(o.x, o.y);
    *reinterpret_cast<__half2*>(g_xh16 + d + 2) = __floats2half2_rn(o.z, o.w);
}

// ---------------------------------------------------------------------------
// Attention per (b,h): scores -> warp-parallel softmax -> AV -> residual
// ---------------------------------------------------------------------------
__global__ void __launch_bounds__(256) attn_kernel() {
    int bh = blockIdx.x;
    int b = bh >> 4;
    int h = bh & 15;
    __shared__ float qs[S][DH + 1];
    __shared__ float ks[S][DH + 1];
    __shared__ float vs[S][DH + 1];
    __shared__ float sc[S][S];
    int tid = threadIdx.x;
    int lane = tid & 31;
    int w = tid >> 5;

    for (int p = tid; p < S * DH; p += 256) {
        int s = p >> 6, d = p & 63;
        size_t g = (size_t)(s * Bn + b) * QKVN + h * DH + d;
        qs[s][d] = g_qkv[g];
        ks[s][d] = g_qkv[g + 1024];
        vs[s][d] = g_qkv[g + 2048];
    }
    __syncthreads();

    constexpr float scale = 0.03125f;   // 1/sqrt(1024)
    for (int p = tid; p < S * S; p += 256) {
        int si = p / S, ti = p - si * S;
        float acc = 0.f;
#pragma unroll
        for (int d = 0; d < DH; d++) acc = fmaf(qs[si][d], ks[ti][d], acc);
        sc[si][ti] = acc * scale;
    }
    __syncthreads();

    // warp-parallel softmax: warp w handles rows w, w+8, w+16
    for (int r = w; r < S; r += 8) {
        float v = (lane < S) ? sc[r][lane] : -1e30f;
        float mx = v;
#pragma unroll
        for (int o = 16; o; o >>= 1) mx = fmaxf(mx, __shfl_xor_sync(0xFFFFFFFFu, mx, o));
        float e = (lane < S) ? expf(v - mx) : 0.f;
        float sum = e;
#pragma unroll
        for (int o = 16; o; o >>= 1) sum += __shfl_xor_sync(0xFFFFFFFFu, sum, o);
        if (lane < S) sc[r][lane] = e * (1.f / sum);
    }
    __syncthreads();

    for (int p = tid; p < S * DH; p += 256) {
        int s = p >> 6, d = p & 63;
        float acc = 0.f;
#pragma unroll
        for (int t = 0; t < S; t++) acc = fmaf(sc[s][t], vs[t][d], acc);
        size_t xi = (size_t)(s * Bn + b) * Dm + h * DH + d;
        float nv = g_x[xi] + acc;
        g_x[xi] = nv;
        g_xh16[xi] = __half_as_ushort(__float2half_rn(nv));
    }
}

// ---------------------------------------------------------------------------
extern "C" void kernel_launch(void* const* d_in, const int* in_sizes, int n_in,
                              void* d_out, int out_size) {
    const int*   inputs = (const int*)d_in[0];
    // d_in[1] = mask (reference drops it)
    const float* tok = (const float*)d_in[2];
    const float* pe  = (const float*)d_in[3];
    const float* qw  = (const float*)d_in[4];
    const float* qb  = (const float*)d_in[5];
    const float* kw  = (const float*)d_in[6];
    const float* kb  = (const float*)d_in[7];
    const float* vw  = (const float*)d_in[8];
    const float* vb  = (const float*)d_in[9];
    const float* ow  = (const float*)d_in[10];
    const float* ob  = (const float*)d_in[11];
    float* out = (float*)d_out;

    cudaFuncSetAttribute(gemm_qkv_tc, cudaFuncAttributeMaxDynamicSharedMemorySize, SMEM_BYTES);
    cudaFuncSetAttribute(gemm_out_tc, cudaFuncAttributeMaxDynamicSharedMemorySize, SMEM_BYTES);

    conv_wqkv16<<<WROWS, 256>>>(qw, kw, vw);
    conv_wout16<<<Vn, 256>>>(ow);
    embed_kernel<<<Mr, 256>>>(inputs, tok, pe);

    for (int l = 0; l < Ln; l++) {
        gemm_qkv_tc<<<dim3(48, 24), 256, SMEM_BYTES>>>(l, qb, kb, vb);
        attn_kernel<<<Bn * 16, 256>>>();
    }
    gemm_out_tc<<<dim3(48, 250), 256, SMEM_BYTES>>>(ob, out);
}

// round 10
// speedup vs baseline: 1.3446x; 1.0291x over previous
#include <cuda_runtime.h>
#include <cuda_fp16.h>
#include <cstdint>

constexpr int S  = 24;
constexpr int Bn = 256;
constexpr int Dm = 1024;
constexpr int Ln = 12;
constexpr int Vn = 32000;
constexpr int DH = 64;
constexpr int Mr = S * Bn;          // 6144
constexpr int QKVN = 3 * Dm;        // 3072
constexpr int WROWS = Ln * QKVN;    // 36864
constexpr size_t MD = (size_t)16 * 256 * 24 * 64;   // elems per q/k/v plane

constexpr int BM = 128, BN = 128, BK = 64, STAGES = 3;
constexpr int STAGE_BYTES = (BM * BK + BN * BK) * 2;      // 32 KB
constexpr int SMEM_BYTES  = STAGES * STAGE_BYTES;         // 96 KB

// ---------------- scratch (device globals; no allocation) ----------------
__device__ float g_x[(size_t)Mr * Dm];
__device__ float g_qkv[3 * MD];                // [mat][h][b][s][d]
__device__ uint16_t g_xh16[(size_t)Mr * Dm];   // fp16 x
__device__ uint16_t g_w16[(size_t)WROWS * Dm]; // fp16 qkv weights
__device__ uint16_t g_ow16[(size_t)Vn * Dm];   // fp16 out_w

__device__ __forceinline__ uint32_t smem_u32(const void* p) {
    uint32_t a;
    asm("{ .reg .u64 t; cvta.to.shared.u64 t, %1; cvt.u32.u64 %0, t; }" : "=r"(a) : "l"(p));
    return a;
}

// xor swizzle for 128-byte rows (BK=64 b16): 16B chunk index xored with row%8
__device__ __forceinline__ uint32_t swz(int row, int g) {
    return (uint32_t)(row * 128 + ((g ^ (row & 7)) << 4));
}

// ---------------------------------------------------------------------------
// fp16 GEMM via mma.sync: C[128,128] = A[128,1024] . W[128,1024]^T + bias
// QKVMAP=false: row-major C (ld = ldC).  QKVMAP=true: scatter into the
// [mat][h][b][s][d] attention layout (row=(s,b), col=(mat,h,d)).
// 256 threads, 8 warps (4m x 2n), warp tile 32x64, cp.async 3-stage.
// ---------------------------------------------------------------------------
template<bool QKVMAP>
__device__ __forceinline__ void gemm_core(
    const uint16_t* __restrict__ A, const uint16_t* __restrict__ W,
    const float* __restrict__ bias, float* __restrict__ C, int ldC,
    int mT, int nT)
{
    constexpr int NIT_ = 16;
    extern __shared__ char smem[];
    const uint32_t sb = smem_u32(smem);
    const int tid = threadIdx.x;
    const int lane = tid & 31;
    const int wid = tid >> 5;
    const int wm = wid & 3;         // warp m index -> rows 32*wm
    const int wn = wid >> 2;        // warp n index -> cols 64*wn

    auto loadStage = [&](int it, int slot) {
        const int k0 = it * BK;
        const uint32_t sa = sb + slot * STAGE_BYTES;
        const uint32_t sw = sa + BM * BK * 2;
#pragma unroll
        for (int i = 0; i < 4; i++) {
            int ch = tid + i * 256;
            int r = ch >> 3, cb = ch & 7;
            const void* gp = A + (size_t)r * Dm + k0 + cb * 8;
            asm volatile("cp.async.cg.shared.global [%0], [%1], 16;"
                         :: "r"(sa + swz(r, cb)), "l"(gp));
        }
#pragma unroll
        for (int i = 0; i < 4; i++) {
            int ch = tid + i * 256;
            int r = ch >> 3, cb = ch & 7;
            const void* gp = W + (size_t)r * Dm + k0 + cb * 8;
            asm volatile("cp.async.cg.shared.global [%0], [%1], 16;"
                         :: "r"(sw + swz(r, cb)), "l"(gp));
        }
        asm volatile("cp.async.commit_group;");
    };

    float acc[2][8][4];
#pragma unroll
    for (int a = 0; a < 2; a++)
#pragma unroll
        for (int b = 0; b < 8; b++)
#pragma unroll
            for (int c = 0; c < 4; c++) acc[a][b][c] = 0.f;

    loadStage(0, 0);
    loadStage(1, 1);

    for (int it = 0; it < NIT_; it++) {
        if (it + 2 < NIT_) asm volatile("cp.async.wait_group 1;");
        else               asm volatile("cp.async.wait_group 0;");
        __syncthreads();
        if (it + 2 < NIT_) loadStage(it + 2, (it + 2) % STAGES);

        const uint32_t sa = sb + (it % STAGES) * STAGE_BYTES;
        const uint32_t sw = sa + BM * BK * 2;
#pragma unroll
        for (int q = 0; q < 4; q++) {           // k16 steps within BK=64
            uint32_t afr[2][4], bfr[8][2];
#pragma unroll
            for (int mi = 0; mi < 2; mi++) {
                int m = wm * 32 + mi * 16 + (lane & 15);
                int g = 2 * q + (lane >> 4);
                asm volatile("ldmatrix.sync.aligned.m8n8.x4.shared.b16 {%0,%1,%2,%3}, [%4];"
                             : "=r"(afr[mi][0]), "=r"(afr[mi][1]),
                               "=r"(afr[mi][2]), "=r"(afr[mi][3])
                             : "r"(sa + swz(m, g)));
            }
#pragma unroll
            for (int nj = 0; nj < 8; nj += 2) {
                int n = wn * 64 + nj * 8 + (lane & 7) + ((lane & 16) >> 1);
                int g = 2 * q + ((lane >> 3) & 1);
                asm volatile("ldmatrix.sync.aligned.m8n8.x4.shared.b16 {%0,%1,%2,%3}, [%4];"
                             : "=r"(bfr[nj][0]), "=r"(bfr[nj][1]),
                               "=r"(bfr[nj + 1][0]), "=r"(bfr[nj + 1][1])
                             : "r"(sw + swz(n, g)));
            }
#pragma unroll
            for (int mi = 0; mi < 2; mi++)
#pragma unroll
                for (int nj = 0; nj < 8; nj++) {
                    asm volatile(
                        "mma.sync.aligned.m16n8k16.row.col.f32.f16.f16.f32 "
                        "{%0,%1,%2,%3}, {%4,%5,%6,%7}, {%8,%9}, {%0,%1,%2,%3};"
                        : "+f"(acc[mi][nj][0]), "+f"(acc[mi][nj][1]),
                          "+f"(acc[mi][nj][2]), "+f"(acc[mi][nj][3])
                        : "r"(afr[mi][0]), "r"(afr[mi][1]),
                          "r"(afr[mi][2]), "r"(afr[mi][3]),
                          "r"(bfr[nj][0]), "r"(bfr[nj][1]));
                }
        }
    }

    // epilogue
    const int r0 = wm * 32 + (lane >> 2);
    const int cl = 2 * (lane & 3);
#pragma unroll
    for (int mi = 0; mi < 2; mi++)
#pragma unroll
        for (int ro = 0; ro < 2; ro++) {
            int rg = mT * 128 + r0 + mi * 16 + ro * 8;     // global row (s*256+b)
#pragma unroll
            for (int nj = 0; nj < 8; nj++) {
                int colL = wn * 64 + nj * 8 + cl;
                float2 o;
                o.x = acc[mi][nj][ro * 2 + 0] + bias[colL];
                o.y = acc[mi][nj][ro * 2 + 1] + bias[colL + 1];
                if (QKVMAP) {
                    int cg  = nT * 128 + colL;
                    int mat = cg >> 10;
                    int hh  = (cg >> 6) & 15;
                    int dd  = cg & 63;
                    int s   = rg >> 8;
                    int bb  = rg & 255;
                    float* dst = C + (size_t)mat * MD
                                 + (size_t)((((hh << 8) + bb) * 24 + s) << 6) + dd;
                    *reinterpret_cast<float2*>(dst) = o;
                } else {
                    *reinterpret_cast<float2*>(
                        C + (size_t)rg * ldC + nT * 128 + colL) = o;
                }
            }
        }
}

// QKV projection (fp16 1-pass, attention-layout epilogue): grid (48, 24)
__global__ void __launch_bounds__(256, 2) gemm_qkv_tc(
    int layer, const float* __restrict__ qb, const float* __restrict__ kb,
    const float* __restrict__ vb)
{
    const int mT = blockIdx.x, nT = blockIdx.y;
    const size_t aOff = (size_t)mT * 128 * Dm;
    const size_t wOff = (size_t)(layer * QKVN + nT * 128) * Dm;
    const int mat = nT >> 3;
    const float* bias = ((mat == 0) ? qb : (mat == 1) ? kb : vb)
                        + (size_t)layer * Dm + (nT & 7) * 128;
    gemm_core<true>(g_xh16 + aOff, g_w16 + wOff, bias, g_qkv, 0, mT, nT);
}

// Final logits (fp16 1-pass): grid (48, 250)
__global__ void __launch_bounds__(256, 2) gemm_out_tc(
    const float* __restrict__ ob, float* __restrict__ out)
{
    const int mT = blockIdx.x, nT = blockIdx.y;
    const size_t aOff = (size_t)mT * 128 * Dm;
    const size_t wOff = (size_t)nT * 128 * Dm;
    gemm_core<false>(g_xh16 + aOff, g_ow16 + wOff, ob + nT * 128, out, Vn, mT, nT);
}

// ---------------------------------------------------------------------------
// Weight prep: fp32 -> fp16
// ---------------------------------------------------------------------------
__global__ void conv_wqkv16(const float* __restrict__ qw, const float* __restrict__ kw,
                            const float* __restrict__ vw) {
    size_t t = (size_t)blockIdx.x * 256 + threadIdx.x;
    size_t e = t * 4;
    int row = (int)(e >> 10);
    int col = (int)(e & 1023);
    int l   = row / 3072;
    int rem = row - l * 3072;
    int mat = rem >> 10;
    int n   = rem & 1023;
    const float* src = ((mat == 0) ? qw : (mat == 1) ? kw : vw)
                       + (((size_t)l * 1024 + n) << 10) + col;
    float4 v = *reinterpret_cast<const float4*>(src);
    size_t d = ((size_t)row << 10) + col;
    *reinterpret_cast<__half2*>(g_w16 + d)     = __floats2half2_rn(v.x, v.y);
    *reinterpret_cast<__half2*>(g_w16 + d + 2) = __floats2half2_rn(v.z, v.w);
}

__global__ void conv_wout16(const float* __restrict__ ow) {
    size_t e = ((size_t)blockIdx.x * 256 + threadIdx.x) * 4;   // < Vn*Dm
    float4 v = *reinterpret_cast<const float4*>(ow + e);
    *reinterpret_cast<__half2*>(g_ow16 + e)     = __floats2half2_rn(v.x, v.y);
    *reinterpret_cast<__half2*>(g_ow16 + e + 2) = __floats2half2_rn(v.z, v.w);
}

// ---------------------------------------------------------------------------
// Embedding + fp16 convert
// ---------------------------------------------------------------------------
__global__ void embed_kernel(const int* __restrict__ inputs,
                             const float* __restrict__ tok,
                             const float* __restrict__ pe) {
    int row = blockIdx.x;          // s*B + b
    int s = row / Bn;
    int t = inputs[row];
    const float4* te = reinterpret_cast<const float4*>(tok + (size_t)t * Dm);
    const float4* pp = reinterpret_cast<const float4*>(pe + (size_t)s * Dm);
    float4 a = te[threadIdx.x];
    float4 b = pp[threadIdx.x];
    float4 o = make_float4(a.x + b.x, a.y + b.y, a.z + b.z, a.w + b.w);
    size_t d = (size_t)row * Dm + threadIdx.x * 4;
    *reinterpret_cast<float4*>(g_x + d) = o;
    *reinterpret_cast<__half2*>(g_xh16 + d)     = __floats2half2_rn(o.x, o.y);
    *reinterpret_cast<__half2*>(g_xh16 + d + 2) = __floats2half2_rn(o.z, o.w);
}

// ---------------------------------------------------------------------------
// Attention per (h,b): fully-contiguous q/k/v loads -> scores -> warp softmax
// -> AV -> residual.  blockIdx.x = h*256 + b (b-major for L2 locality).
// ---------------------------------------------------------------------------
__global__ void __launch_bounds__(256) attn_kernel() {
    int bh = blockIdx.x;
    int b = bh & 255;
    int h = bh >> 8;
    __shared__ float qs[S][DH + 1];
    __shared__ float ks[S][DH + 1];
    __shared__ float vs[S][DH + 1];
    __shared__ float sc[S][S];
    int tid = threadIdx.x;
    int lane = tid & 31;
    int w = tid >> 5;

    const float* qp = g_qkv + (size_t)(((h << 8) + b) * 24) * 64;   // 1536 floats
    const float* kp = qp + MD;
    const float* vp = qp + 2 * MD;
    for (int p = tid; p < S * DH / 4; p += 256) {     // 384 float4 per matrix
        int s = p >> 4, d4 = (p & 15) * 4;
        float4 q4 = reinterpret_cast<const float4*>(qp)[p];
        float4 k4 = reinterpret_cast<const float4*>(kp)[p];
        float4 v4 = reinterpret_cast<const float4*>(vp)[p];
        qs[s][d4] = q4.x; qs[s][d4 + 1] = q4.y; qs[s][d4 + 2] = q4.z; qs[s][d4 + 3] = q4.w;
        ks[s][d4] = k4.x; ks[s][d4 + 1] = k4.y; ks[s][d4 + 2] = k4.z; ks[s][d4 + 3] = k4.w;
        vs[s][d4] = v4.x; vs[s][d4 + 1] = v4.y; vs[s][d4 + 2] = v4.z; vs[s][d4 + 3] = v4.w;
    }
    __syncthreads();

    constexpr float scale = 0.03125f;   // 1/sqrt(1024)
    for (int p = tid; p < S * S; p += 256) {
        int si = p / S, ti = p - si * S;
        float acc = 0.f;
#pragma unroll
        for (int d = 0; d < DH; d++) acc = fmaf(qs[si][d], ks[ti][d], acc);
        sc[si][ti] = acc * scale;
    }
    __syncthreads();

    // warp-parallel softmax: warp w handles rows w, w+8, w+16
    for (int r = w; r < S; r += 8) {
        float v = (lane < S) ? sc[r][lane] : -1e30f;
        float mx = v;
#pragma unroll
        for (int o = 16; o; o >>= 1) mx = fmaxf(mx, __shfl_xor_sync(0xFFFFFFFFu, mx, o));
        float e = (lane < S) ? expf(v - mx) : 0.f;
        float sum = e;
#pragma unroll
        for (int o = 16; o; o >>= 1) sum += __shfl_xor_sync(0xFFFFFFFFu, sum, o);
        if (lane < S) sc[r][lane] = e * (1.f / sum);
    }
    __syncthreads();

    for (int p = tid; p < S * DH; p += 256) {
        int s = p >> 6, d = p & 63;
        float acc = 0.f;
#pragma unroll
        for (int t = 0; t < S; t++) acc = fmaf(sc[s][t], vs[t][d], acc);
        size_t xi = (size_t)(s * Bn + b) * Dm + h * DH + d;
        float nv = g_x[xi] + acc;
        g_x[xi] = nv;
        g_xh16[xi] = __half_as_ushort(__float2half_rn(nv));
    }
}

// ---------------------------------------------------------------------------
extern "C" void kernel_launch(void* const* d_in, const int* in_sizes, int n_in,
                              void* d_out, int out_size) {
    const int*   inputs = (const int*)d_in[0];
    // d_in[1] = mask (reference drops it)
    const float* tok = (const float*)d_in[2];
    const float* pe  = (const float*)d_in[3];
    const float* qw  = (const float*)d_in[4];
    const float* qb  = (const float*)d_in[5];
    const float* kw  = (const float*)d_in[6];
    const float* kb  = (const float*)d_in[7];
    const float* vw  = (const float*)d_in[8];
    const float* vb  = (const float*)d_in[9];
    const float* ow  = (const float*)d_in[10];
    const float* ob  = (const float*)d_in[11];
    float* out = (float*)d_out;

    cudaFuncSetAttribute(gemm_qkv_tc, cudaFuncAttributeMaxDynamicSharedMemorySize, SMEM_BYTES);
    cudaFuncSetAttribute(gemm_out_tc, cudaFuncAttributeMaxDynamicSharedMemorySize, SMEM_BYTES);

    conv_wqkv16<<<WROWS, 256>>>(qw, kw, vw);
    conv_wout16<<<Vn, 256>>>(ow);
    embed_kernel<<<Mr, 256>>>(inputs, tok, pe);

    for (int l = 0; l < Ln; l++) {
        gemm_qkv_tc<<<dim3(48, 24), 256, SMEM_BYTES>>>(l, qb, kb, vb);
        attn_kernel<<<Bn * 16, 256>>>();
    }
    gemm_out_tc<<<dim3(48, 250), 256, SMEM_BYTES>>>(ob, out);
}